// round 11
// baseline (speedup 1.0000x reference)
#include <cuda_runtime.h>
#include <cuda_bf16.h>
#include <cstdint>

typedef unsigned long long u64;

// ---------------- static scratch ----------------
// activations layout: (p, b, c) : act[(p*128 + b)*256 + c]
__device__ __align__(16) float g_bufA[512 * 128 * 256];   // 67 MB
__device__ __align__(16) float g_bufB[256 * 128 * 256];   // 33.5 MB
__device__ __align__(16) float g_part[4194304];           // 16.8 MB split-K partials
__device__ unsigned g_sync = 0;

// ---------------- helpers ----------------
__device__ __forceinline__ uint32_t s2u(const void* p) {
    uint32_t a;
    asm("{\n\t.reg .u64 t;\n\tcvta.to.shared.u64 t, %1;\n\tcvt.u32.u64 %0, t;\n\t}" : "=r"(a) : "l"(p));
    return a;
}
__device__ __forceinline__ uint32_t packbf(float lo, float hi) {
    uint32_t r;
    asm("cvt.rn.bf16x2.f32 %0, %1, %2;" : "=r"(r) : "f"(hi), "f"(lo));
    return r;
}
__device__ __forceinline__ void split2(float x0, float x1, uint32_t& hi, uint32_t& lo) {
    uint32_t h = packbf(x0, x1);
    __nv_bfloat162 h2 = *(__nv_bfloat162*)&h;
    lo = packbf(x0 - __bfloat162float(h2.x), x1 - __bfloat162float(h2.y));
    hi = h;
}
__device__ __forceinline__ void ldsm4(uint32_t* r, uint32_t addr) {
    asm volatile("ldmatrix.sync.aligned.m8n8.x4.shared.b16 {%0,%1,%2,%3}, [%4];"
        : "=r"(r[0]), "=r"(r[1]), "=r"(r[2]), "=r"(r[3]) : "r"(addr));
}
__device__ __forceinline__ void mma16816(float* d, const uint32_t* a, uint32_t b0, uint32_t b1) {
    asm volatile("mma.sync.aligned.m16n8k16.row.col.f32.bf16.bf16.f32 "
        "{%0,%1,%2,%3}, {%4,%5,%6,%7}, {%8,%9}, {%0,%1,%2,%3};"
        : "+f"(d[0]), "+f"(d[1]), "+f"(d[2]), "+f"(d[3])
        : "r"(a[0]), "r"(a[1]), "r"(a[2]), "r"(a[3]), "r"(b0), "r"(b1));
}
__device__ __forceinline__ void grid_sync(int goal) {
    __syncthreads();
    if (threadIdx.x == 0) {
        __threadfence();
        atomicAdd(&g_sync, 1u);
        unsigned v;
        do {
            asm volatile("ld.volatile.global.u32 %0, [%1];" : "=r"(v) : "l"(&g_sync));
            if (v < (unsigned)goal) __nanosleep(64);
        } while (v < (unsigned)goal);
    }
    __syncthreads();
}

// ---------------- layer 0 ----------------
__global__ void layer0_kernel(const float* __restrict__ x, const float* __restrict__ w0,
                              float* __restrict__ out)
{
    __shared__ float xs[6][128];
    const int d   = blockIdx.x;
    const int tid = threadIdx.x;
#pragma unroll
    for (int i = 0; i < 3; i++) {
        int e = tid + i * 256;
        int ck = e >> 7, b = e & 127;
        int c = ck >> 1, k = ck & 1;
        xs[ck][b] = x[(b * 3 + c) * 1024 + 2 * d + k];
    }
    __syncthreads();
    const int b  = tid & 127;
    const int oh = tid >> 7;
    const float2* w2 = (const float2*)w0;
    for (int o = oh; o < 256; o += 2) {
        float acc = 0.f;
#pragma unroll
        for (int c = 0; c < 3; c++) {
            float2 wv = w2[(o * 3 + c) * 512 + d];
            acc += xs[c * 2 + 0][b] * wv.x + xs[c * 2 + 1][b] * wv.y;
        }
        out[((size_t)d * 128 + b) * 256 + o] = fmaxf(acc * 0.5773502691896258f, 0.f);
    }
}

// ---------------- GEMM body (R10, parameterized s,d) ----------------
// in : (p, b, c); w : (256,256,dl,2). CTA: M=128 x N=256 x K-slice (nst*32 kappa)
#define SMEM_BYTES 98304

__device__ __forceinline__ void gemm_body(
    const float* __restrict__ in, const float* __restrict__ w,
    float* __restrict__ actout, int dl, int nst, float scale, int partial,
    int s, int d, char* smem)
{
    const uint32_t sb = s2u(smem);
    const int tid  = threadIdx.x;
    const int wid  = tid >> 5, lane = tid & 31;
    const int cbase = s * nst * 16;

    // ---- A loader roles ----
    const int r  = tid >> 1;
    const int h  = tid & 1;
    const float*  a0p = in + ((size_t)(2 * d) * 128 + r) * 256;
    const float*  a1p = a0p + 128 * 256;
    const uint32_t rowb = (uint32_t)r * 128, xs_ = (uint32_t)(r & 7) << 4;
    const uint32_t offH0 = rowb + (((uint32_t)(2 * h) * 16) ^ xs_);
    const uint32_t offH1 = rowb + (((uint32_t)(2 * h + 1) * 16) ^ xs_);
    const uint32_t offL0 = rowb + (((uint32_t)(4 + 2 * h) * 16) ^ xs_);
    const uint32_t offL1 = rowb + (((uint32_t)(5 + 2 * h) * 16) ^ xs_);

    // ---- B loader roles ----
    const int ob = tid;
    const float2* w2 = (const float2*)w;
    const size_t  wrow = (size_t)ob * 256;
    const uint32_t rowbB = (uint32_t)ob * 128, xsB = (uint32_t)(ob & 7) << 4;
    uint32_t offBH[4], offBL[4];
#pragma unroll
    for (int g = 0; g < 4; g++) {
        offBH[g] = rowbB + (((uint32_t)(g * 16)) ^ xsB);
        offBL[g] = rowbB + (((uint32_t)(64 + g * 16)) ^ xsB);
    }

    const uint32_t ST[2] = { sb, sb + 49152 };

    // ---- compute roles: 2(M) x 4(N) warps, warp tile 64x64 ----
    const int mh = wid & 1, nq = wid >> 1;
    const uint32_t co = (uint32_t)(lane >> 4) * 16;
    const uint32_t xa = (uint32_t)(lane & 7) << 4;
    uint32_t rA[4], rB[4];
#pragma unroll
    for (int mi = 0; mi < 4; mi++) rA[mi] = (uint32_t)(mh * 64 + mi * 16 + (lane & 15)) * 128;
#pragma unroll
    for (int bj = 0; bj < 4; bj++) rB[bj] = (uint32_t)(nq * 64 + bj * 16 + (lane & 15)) * 128;

    float D[4][8][4];
#pragma unroll
    for (int i = 0; i < 4; i++)
#pragma unroll
        for (int j = 0; j < 8; j++)
#pragma unroll
            for (int q = 0; q < 4; q++) D[i][j][q] = 0.f;

    float  fa[16];
    float2 fb[16];

    auto issue_loads = [&](int t) {
        const int c0a = cbase + t * 16 + 8 * h;
        *(float4*)&fa[0]  = __ldcg((const float4*)(a0p + c0a));
        *(float4*)&fa[4]  = __ldcg((const float4*)(a0p + c0a + 4));
        *(float4*)&fa[8]  = __ldcg((const float4*)(a1p + c0a));
        *(float4*)&fa[12] = __ldcg((const float4*)(a1p + c0a + 4));
        const int c0b = cbase + t * 16;
#pragma unroll
        for (int j = 0; j < 16; j++)
            fb[j] = w2[(wrow + (size_t)(c0b + j)) * dl + d];
    };

    auto convert_store = [&](int buf) {
        uint32_t Ah[8], Al[8];
#pragma unroll
        for (int j = 0; j < 8; j++)
            split2(fa[j], fa[8 + j], Ah[j], Al[j]);
        const uint32_t ab = ST[buf];
        asm volatile("st.shared.v4.b32 [%0], {%1,%2,%3,%4};" :: "r"(ab + offH0), "r"(Ah[0]), "r"(Ah[1]), "r"(Ah[2]), "r"(Ah[3]));
        asm volatile("st.shared.v4.b32 [%0], {%1,%2,%3,%4};" :: "r"(ab + offH1), "r"(Ah[4]), "r"(Ah[5]), "r"(Ah[6]), "r"(Ah[7]));
        asm volatile("st.shared.v4.b32 [%0], {%1,%2,%3,%4};" :: "r"(ab + offL0), "r"(Al[0]), "r"(Al[1]), "r"(Al[2]), "r"(Al[3]));
        asm volatile("st.shared.v4.b32 [%0], {%1,%2,%3,%4};" :: "r"(ab + offL1), "r"(Al[4]), "r"(Al[5]), "r"(Al[6]), "r"(Al[7]));
        const uint32_t bbx = ST[buf] + 16384;
#pragma unroll
        for (int g = 0; g < 4; g++) {
            uint32_t BH[4], BL[4];
#pragma unroll
            for (int m = 0; m < 4; m++)
                split2(fb[g * 4 + m].x, fb[g * 4 + m].y, BH[m], BL[m]);
            asm volatile("st.shared.v4.b32 [%0], {%1,%2,%3,%4};" :: "r"(bbx + offBH[g]), "r"(BH[0]), "r"(BH[1]), "r"(BH[2]), "r"(BH[3]));
            asm volatile("st.shared.v4.b32 [%0], {%1,%2,%3,%4};" :: "r"(bbx + offBL[g]), "r"(BL[0]), "r"(BL[1]), "r"(BL[2]), "r"(BL[3]));
        }
    };

    issue_loads(0);
    convert_store(0);
    __syncthreads();

    for (int t = 0; t < nst; t++) {
        const int buf = t & 1;
        if (t + 1 < nst) issue_loads(t + 1);

        const uint32_t ab = ST[buf], bb = ST[buf] + 16384;
#pragma unroll
        for (int kk = 0; kk < 2; kk++) {
            const uint32_t khi = (uint32_t)(32 * kk) + co;
            const uint32_t klo = khi + 64;
            uint32_t Ahf[4][4], Alf[4][4];
#pragma unroll
            for (int mi = 0; mi < 4; mi++) {
                ldsm4(Ahf[mi], ab + rA[mi] + (khi ^ xa));
                ldsm4(Alf[mi], ab + rA[mi] + (klo ^ xa));
            }
#pragma unroll
            for (int bj = 0; bj < 4; bj++) {
                uint32_t Bhf[4], Blf[4];
                ldsm4(Bhf, bb + rB[bj] + (khi ^ xa));
                ldsm4(Blf, bb + rB[bj] + (klo ^ xa));
#pragma unroll
                for (int mi = 0; mi < 4; mi++) {
#pragma unroll
                    for (int ns = 0; ns < 2; ns++) {
                        float* dd = D[mi][bj * 2 + ns];
                        mma16816(dd, Ahf[mi], Bhf[ns], Bhf[ns + 2]);
                        mma16816(dd, Alf[mi], Bhf[ns], Bhf[ns + 2]);
                        mma16816(dd, Ahf[mi], Blf[ns], Blf[ns + 2]);
                    }
                }
            }
        }

        if (t + 1 < nst) convert_store(buf ^ 1);
        __syncthreads();
    }

    // ---- epilogue ----
    const int colq = nq * 64 + 2 * (lane & 3);
    if (partial) {
        float* pp = g_part + ((size_t)s * dl + d) * 32768;
#pragma unroll
        for (int mi = 0; mi < 4; mi++) {
            const int b0 = mh * 64 + mi * 16 + (lane >> 2);
#pragma unroll
            for (int nj = 0; nj < 8; nj++) {
                const int col = colq + nj * 8;
                *(float2*)(pp + (size_t)b0 * 256 + col)       = make_float2(D[mi][nj][0], D[mi][nj][1]);
                *(float2*)(pp + (size_t)(b0 + 8) * 256 + col) = make_float2(D[mi][nj][2], D[mi][nj][3]);
            }
        }
    } else {
        float* op = actout + (size_t)d * 128 * 256;
#pragma unroll
        for (int mi = 0; mi < 4; mi++) {
            const int b0 = mh * 64 + mi * 16 + (lane >> 2);
#pragma unroll
            for (int nj = 0; nj < 8; nj++) {
                const int col = colq + nj * 8;
                float2 v0 = make_float2(fmaxf(D[mi][nj][0] * scale, 0.f), fmaxf(D[mi][nj][1] * scale, 0.f));
                float2 v1 = make_float2(fmaxf(D[mi][nj][2] * scale, 0.f), fmaxf(D[mi][nj][3] * scale, 0.f));
                *(float2*)(op + (size_t)b0 * 256 + col)       = v0;
                *(float2*)(op + (size_t)(b0 + 8) * 256 + col) = v1;
            }
        }
    }
}

// ---------------- named per-layer GEMM kernels (ncu disambiguation) ----------------
template<int TAG>
__global__ __launch_bounds__(256)
void lc_mma(const float* __restrict__ in, const float* __restrict__ w,
            float* __restrict__ out, int dl, int nst, float scale, int partial)
{
    extern __shared__ __align__(1024) char smem[];
    gemm_body(in, w, out, dl, nst, scale, partial, blockIdx.y, blockIdx.x, smem);
}

// ---------------- split-K reduce + relu (host-launched, L3 only) ----------------
__global__ void reduce_relu_kernel(const float* __restrict__ part, float* __restrict__ out,
                                   int n, int dl, int S, float scale)
{
    int idx = blockIdx.x * 256 + threadIdx.x;
    if (idx >= n) return;
    const int dd  = idx >> 15;
    const int rem = idx & 32767;
    float sum = 0.f;
    for (int si = 0; si < S; si++)
        sum += part[((size_t)si * dl + dd) * 32768 + rem];
    out[idx] = fmaxf(sum * scale, 0.f);
}

// ---------------- persistent fused tail: layers 4..9 (dl=32..1) + head ----------------
__global__ __launch_bounds__(256)
void lc_tail(float* buf0, float* buf1,
             const float* w4, const float* w5, const float* w6, const float* w7,
             const float* w8, const float* w9,
             const float* __restrict__ beta, float* __restrict__ out, float scale)
{
    extern __shared__ __align__(1024) char smem[];
    const float* Wl[6] = { w4, w5, w6, w7, w8, w9 };
    float* cur = buf0;
    float* nxt = buf1;
    int dl = 32;
    int goal = 0;
    const int gtid = blockIdx.x * 256 + threadIdx.x;

    for (int L = 0; L < 6; L++) {
        int S = 128 / dl; if (S > 16) S = 16;
        const int nst = 16 / S;
        const int active = dl * S;
        if ((int)blockIdx.x < active) {
            const int d = blockIdx.x % dl;
            const int s = blockIdx.x / dl;
            gemm_body(cur, Wl[L], nullptr, dl, nst, scale, 1, s, d, smem);
        }
        goal += 128; grid_sync(goal);

        const int n = dl * 32768;
        for (int idx = gtid; idx < n; idx += 32768) {
            const int dd = idx >> 15, rem = idx & 32767;
            float sum = 0.f;
            for (int si = 0; si < S; si++)
                sum += __ldcg(&g_part[((size_t)si * dl + dd) * 32768 + rem]);
            nxt[idx] = fmaxf(sum * scale, 0.f);
        }
        goal += 128; grid_sync(goal);

        float* tmp = cur; cur = nxt; nxt = tmp;
        dl >>= 1;
    }

    // head: out[b,t] = (1/256) sum_o act[b,o] * beta[o,t]
    if (blockIdx.x < 10 && threadIdx.x < 128) {
        const int t = blockIdx.x, b = threadIdx.x;
        float ssum = 0.f;
#pragma unroll 8
        for (int o = 0; o < 256; o++)
            ssum += __ldcg(&cur[b * 256 + o]) * __ldg(&beta[o * 10 + t]);
        out[b * 10 + t] = ssum * (1.0f / 256.0f);
    }
    if (blockIdx.x == 127 && threadIdx.x == 0)
        atomicExch(&g_sync, 0u);   // reset for next graph replay
}

// ---------------- launch ----------------
extern "C" void kernel_launch(void* const* d_in, const int* in_sizes, int n_in,
                              void* d_out, int out_size)
{
    const float* x = (const float*)d_in[0];
    const float* wl[10];
    for (int l = 0; l < 10; l++) wl[l] = (const float*)d_in[1 + l];
    const float* beta = (const float*)d_in[11];
    float* out = (float*)d_out;

    float *bufA, *bufB, *part;
    cudaGetSymbolAddress((void**)&bufA, g_bufA);
    cudaGetSymbolAddress((void**)&bufB, g_bufB);
    cudaGetSymbolAddress((void**)&part, g_part);

    cudaFuncSetAttribute(lc_mma<1>, cudaFuncAttributeMaxDynamicSharedMemorySize, SMEM_BYTES);
    cudaFuncSetAttribute(lc_mma<2>, cudaFuncAttributeMaxDynamicSharedMemorySize, SMEM_BYTES);
    cudaFuncSetAttribute(lc_mma<3>, cudaFuncAttributeMaxDynamicSharedMemorySize, SMEM_BYTES);
    cudaFuncSetAttribute(lc_tail,   cudaFuncAttributeMaxDynamicSharedMemorySize, SMEM_BYTES);

    const float scale = 0.0625f;

    layer0_kernel<<<512, 256>>>(x, wl[0], bufA);

    // L1: dl=256, S=1
    lc_mma<1><<<dim3(256, 1), 256, SMEM_BYTES>>>(bufA, wl[1], bufB, 256, 16, scale, 0);
    // L2: dl=128, S=1
    lc_mma<2><<<dim3(128, 1), 256, SMEM_BYTES>>>(bufB, wl[2], bufA, 128, 16, scale, 0);
    // L3: dl=64, S=2 (partials) + reduce -> bufB
    lc_mma<3><<<dim3(64, 2), 256, SMEM_BYTES>>>(bufA, wl[3], bufA, 64, 8, scale, 1);
    {
        const int n = 64 * 32768;
        reduce_relu_kernel<<<(n + 255) / 256, 256>>>(part, bufB, n, 64, 2, scale);
    }
    // L4..L9 + head, persistent
    lc_tail<<<128, 256, SMEM_BYTES>>>(bufB, bufA,
                                      wl[4], wl[5], wl[6], wl[7], wl[8], wl[9],
                                      beta, out, scale);
}

// round 12
// speedup vs baseline: 1.0036x; 1.0036x over previous
#include <cuda_runtime.h>
#include <cuda_fp16.h>
#include <cstdint>

typedef unsigned long long u64;

// ---------------- static scratch ----------------
// activations layout: (p, b, c) : act[(p*128 + b)*256 + c]
__device__ __align__(16) float g_bufA[512 * 128 * 256];   // 67 MB
__device__ __align__(16) float g_bufB[256 * 128 * 256];   // 33.5 MB
__device__ __align__(16) float g_part[4194304];           // 16.8 MB split-K partials

// ---------------- helpers ----------------
__device__ __forceinline__ uint32_t s2u(const void* p) {
    uint32_t a;
    asm("{\n\t.reg .u64 t;\n\tcvta.to.shared.u64 t, %1;\n\tcvt.u32.u64 %0, t;\n\t}" : "=r"(a) : "l"(p));
    return a;
}
// pack two f32 -> f16x2: first arg -> low half, second -> high half
__device__ __forceinline__ uint32_t packh(float lo, float hi) {
    uint32_t r;
    asm("cvt.rn.f16x2.f32 %0, %1, %2;" : "=r"(r) : "f"(hi), "f"(lo));
    return r;
}
__device__ __forceinline__ void split2(float x0, float x1, uint32_t& hi, uint32_t& lo) {
    uint32_t h = packh(x0, x1);
    __half2 h2 = *(__half2*)&h;
    float r0 = x0 - __half2float(h2.x);
    float r1 = x1 - __half2float(h2.y);
    lo = packh(r0, r1);
    hi = h;
}
__device__ __forceinline__ void ldsm4(uint32_t* r, uint32_t addr) {
    asm volatile("ldmatrix.sync.aligned.m8n8.x4.shared.b16 {%0,%1,%2,%3}, [%4];"
        : "=r"(r[0]), "=r"(r[1]), "=r"(r[2]), "=r"(r[3]) : "r"(addr));
}
__device__ __forceinline__ void mma16816(float* d, const uint32_t* a, uint32_t b0, uint32_t b1) {
    asm volatile("mma.sync.aligned.m16n8k16.row.col.f32.f16.f16.f32 "
        "{%0,%1,%2,%3}, {%4,%5,%6,%7}, {%8,%9}, {%0,%1,%2,%3};"
        : "+f"(d[0]), "+f"(d[1]), "+f"(d[2]), "+f"(d[3])
        : "r"(a[0]), "r"(a[1]), "r"(a[2]), "r"(a[3]), "r"(b0), "r"(b1));
}

// ---------------- layer 0 ----------------
__global__ void layer0_kernel(const float* __restrict__ x, const float* __restrict__ w0,
                              float* __restrict__ out)
{
    __shared__ float xs[6][128];
    const int d   = blockIdx.x;
    const int tid = threadIdx.x;
#pragma unroll
    for (int i = 0; i < 3; i++) {
        int e = tid + i * 256;
        int ck = e >> 7, b = e & 127;
        int c = ck >> 1, k = ck & 1;
        xs[ck][b] = x[(b * 3 + c) * 1024 + 2 * d + k];
    }
    __syncthreads();
    const int b  = tid & 127;
    const int oh = tid >> 7;
    const float2* w2 = (const float2*)w0;
    for (int o = oh; o < 256; o += 2) {
        float acc = 0.f;
#pragma unroll
        for (int c = 0; c < 3; c++) {
            float2 wv = w2[(o * 3 + c) * 512 + d];
            acc += xs[c * 2 + 0][b] * wv.x + xs[c * 2 + 1][b] * wv.y;
        }
        out[((size_t)d * 128 + b) * 256 + o] = fmaxf(acc * 0.5773502691896258f, 0.f);
    }
}

// ---------------- layers 1..9: warp-mma fp16x3, CTA 128x256, warp tile 64x64 ----------------
// in : (p, b, c)  C=256, B=128 ; w : (256, 256, dl, 2)
// CTA: M=128(b) x N=256(all o) x K-slice (nst*32), kappa = 2c+k
// smem stage: A tile 128x128B (16KB) + B tile 256x128B (32KB)
// Row layout: linear kappa — bytes [0,64) hi plane, [64,128) lo plane; SW128 swizzle.
#define SMEM_BYTES 98304

__global__ __launch_bounds__(256)
void lc_mma(const float* __restrict__ in, const float* __restrict__ w,
            float* __restrict__ out, int dl, int nst, float scale, int partial)
{
    extern __shared__ __align__(1024) char smem[];
    const uint32_t sb = s2u(smem);
    const int tid  = threadIdx.x;
    const int wid  = tid >> 5, lane = tid & 31;
    const int d    = blockIdx.x;
    const int s    = blockIdx.y;
    const int cbase = s * nst * 16;

    // ---- A loader roles: row r = b, channel-half h ----
    const int r  = tid >> 1;
    const int h  = tid & 1;
    const float*  a0p = in + ((size_t)(2 * d) * 128 + r) * 256;
    const float*  a1p = a0p + 128 * 256;
    const uint32_t rowb = (uint32_t)r * 128, xs_ = (uint32_t)(r & 7) << 4;
    const uint32_t offH0 = rowb + (((uint32_t)(2 * h) * 16) ^ xs_);
    const uint32_t offH1 = rowb + (((uint32_t)(2 * h + 1) * 16) ^ xs_);
    const uint32_t offL0 = rowb + (((uint32_t)(4 + 2 * h) * 16) ^ xs_);
    const uint32_t offL1 = rowb + (((uint32_t)(5 + 2 * h) * 16) ^ xs_);

    // ---- B loader roles: one thread per o row ----
    const int ob = tid;
    const float2* w2 = (const float2*)w;
    const size_t  wrow = (size_t)ob * 256;
    const uint32_t rowbB = (uint32_t)ob * 128, xsB = (uint32_t)(ob & 7) << 4;
    uint32_t offBH[4], offBL[4];
#pragma unroll
    for (int g = 0; g < 4; g++) {
        offBH[g] = rowbB + (((uint32_t)(g * 16)) ^ xsB);
        offBL[g] = rowbB + (((uint32_t)(64 + g * 16)) ^ xsB);
    }

    const uint32_t ST[2] = { sb, sb + 49152 };

    // ---- compute roles: 2(M) x 4(N) warps, warp tile 64x64 ----
    const int mh = wid & 1, nq = wid >> 1;
    const uint32_t co = (uint32_t)(lane >> 4) * 16;
    const uint32_t xa = (uint32_t)(lane & 7) << 4;
    uint32_t rA[4], rB[4];
#pragma unroll
    for (int mi = 0; mi < 4; mi++) rA[mi] = (uint32_t)(mh * 64 + mi * 16 + (lane & 15)) * 128;
#pragma unroll
    for (int bj = 0; bj < 4; bj++) rB[bj] = (uint32_t)(nq * 64 + bj * 16 + (lane & 15)) * 128;

    float D[4][8][4];
#pragma unroll
    for (int i = 0; i < 4; i++)
#pragma unroll
        for (int j = 0; j < 8; j++)
#pragma unroll
            for (int q = 0; q < 4; q++) D[i][j][q] = 0.f;

    float  fa[16];
    float2 fb[16];

    auto issue_loads = [&](int t) {
        const int c0a = cbase + t * 16 + 8 * h;
        *(float4*)&fa[0]  = *(const float4*)(a0p + c0a);
        *(float4*)&fa[4]  = *(const float4*)(a0p + c0a + 4);
        *(float4*)&fa[8]  = *(const float4*)(a1p + c0a);
        *(float4*)&fa[12] = *(const float4*)(a1p + c0a + 4);
        const int c0b = cbase + t * 16;
#pragma unroll
        for (int j = 0; j < 16; j++)
            fb[j] = w2[(wrow + (size_t)(c0b + j)) * dl + d];
    };

    auto convert_store = [&](int buf) {
        uint32_t Ah[8], Al[8];
#pragma unroll
        for (int j = 0; j < 8; j++)
            split2(fa[j], fa[8 + j], Ah[j], Al[j]);
        const uint32_t ab = ST[buf];
        asm volatile("st.shared.v4.b32 [%0], {%1,%2,%3,%4};" :: "r"(ab + offH0), "r"(Ah[0]), "r"(Ah[1]), "r"(Ah[2]), "r"(Ah[3]));
        asm volatile("st.shared.v4.b32 [%0], {%1,%2,%3,%4};" :: "r"(ab + offH1), "r"(Ah[4]), "r"(Ah[5]), "r"(Ah[6]), "r"(Ah[7]));
        asm volatile("st.shared.v4.b32 [%0], {%1,%2,%3,%4};" :: "r"(ab + offL0), "r"(Al[0]), "r"(Al[1]), "r"(Al[2]), "r"(Al[3]));
        asm volatile("st.shared.v4.b32 [%0], {%1,%2,%3,%4};" :: "r"(ab + offL1), "r"(Al[4]), "r"(Al[5]), "r"(Al[6]), "r"(Al[7]));
        const uint32_t bbx = ST[buf] + 16384;
#pragma unroll
        for (int g = 0; g < 4; g++) {
            uint32_t BH[4], BL[4];
#pragma unroll
            for (int m = 0; m < 4; m++)
                split2(fb[g * 4 + m].x, fb[g * 4 + m].y, BH[m], BL[m]);
            asm volatile("st.shared.v4.b32 [%0], {%1,%2,%3,%4};" :: "r"(bbx + offBH[g]), "r"(BH[0]), "r"(BH[1]), "r"(BH[2]), "r"(BH[3]));
            asm volatile("st.shared.v4.b32 [%0], {%1,%2,%3,%4};" :: "r"(bbx + offBL[g]), "r"(BL[0]), "r"(BL[1]), "r"(BL[2]), "r"(BL[3]));
        }
    };

    issue_loads(0);
    convert_store(0);
    __syncthreads();

    for (int t = 0; t < nst; t++) {
        const int buf = t & 1;
        if (t + 1 < nst) issue_loads(t + 1);

        const uint32_t ab = ST[buf], bb = ST[buf] + 16384;
#pragma unroll
        for (int kk = 0; kk < 2; kk++) {
            const uint32_t khi = (uint32_t)(32 * kk) + co;
            const uint32_t klo = khi + 64;
            uint32_t Ahf[4][4], Alf[4][4];
#pragma unroll
            for (int mi = 0; mi < 4; mi++) {
                ldsm4(Ahf[mi], ab + rA[mi] + (khi ^ xa));
                ldsm4(Alf[mi], ab + rA[mi] + (klo ^ xa));
            }
#pragma unroll
            for (int bj = 0; bj < 4; bj++) {
                uint32_t Bhf[4], Blf[4];
                ldsm4(Bhf, bb + rB[bj] + (khi ^ xa));
                ldsm4(Blf, bb + rB[bj] + (klo ^ xa));
                // three sweeps of 8 independent MMAs each:
                // same-accumulator writes are 8 issues apart (no RAW back-to-back)
#pragma unroll
                for (int mi = 0; mi < 4; mi++)
#pragma unroll
                    for (int ns = 0; ns < 2; ns++)
                        mma16816(D[mi][bj * 2 + ns], Ahf[mi], Bhf[ns], Bhf[ns + 2]);
#pragma unroll
                for (int mi = 0; mi < 4; mi++)
#pragma unroll
                    for (int ns = 0; ns < 2; ns++)
                        mma16816(D[mi][bj * 2 + ns], Alf[mi], Bhf[ns], Bhf[ns + 2]);
#pragma unroll
                for (int mi = 0; mi < 4; mi++)
#pragma unroll
                    for (int ns = 0; ns < 2; ns++)
                        mma16816(D[mi][bj * 2 + ns], Ahf[mi], Blf[ns], Blf[ns + 2]);
            }
        }

        if (t + 1 < nst) convert_store(buf ^ 1);
        __syncthreads();
    }

    // ---- epilogue ----
    const int colq = nq * 64 + 2 * (lane & 3);
    if (partial) {
        float* pp = g_part + ((size_t)s * dl + d) * 32768;
#pragma unroll
        for (int mi = 0; mi < 4; mi++) {
            const int b0 = mh * 64 + mi * 16 + (lane >> 2);
#pragma unroll
            for (int nj = 0; nj < 8; nj++) {
                const int col = colq + nj * 8;
                *(float2*)(pp + (size_t)b0 * 256 + col)       = make_float2(D[mi][nj][0], D[mi][nj][1]);
                *(float2*)(pp + (size_t)(b0 + 8) * 256 + col) = make_float2(D[mi][nj][2], D[mi][nj][3]);
            }
        }
    } else {
        float* op = out + (size_t)d * 128 * 256;
#pragma unroll
        for (int mi = 0; mi < 4; mi++) {
            const int b0 = mh * 64 + mi * 16 + (lane >> 2);
#pragma unroll
            for (int nj = 0; nj < 8; nj++) {
                const int col = colq + nj * 8;
                float2 v0 = make_float2(fmaxf(D[mi][nj][0] * scale, 0.f), fmaxf(D[mi][nj][1] * scale, 0.f));
                float2 v1 = make_float2(fmaxf(D[mi][nj][2] * scale, 0.f), fmaxf(D[mi][nj][3] * scale, 0.f));
                *(float2*)(op + (size_t)b0 * 256 + col)       = v0;
                *(float2*)(op + (size_t)(b0 + 8) * 256 + col) = v1;
            }
        }
    }
}

// ---------------- split-K reduce + relu ----------------
__global__ void reduce_relu_kernel(const float* __restrict__ part, float* __restrict__ out,
                                   int n, int dl, int S, float scale)
{
    int idx = blockIdx.x * 256 + threadIdx.x;
    if (idx >= n) return;
    const int dd  = idx >> 15;
    const int rem = idx & 32767;
    float sum = 0.f;
    for (int si = 0; si < S; si++)
        sum += part[((size_t)si * dl + dd) * 32768 + rem];
    out[idx] = fmaxf(sum * scale, 0.f);
}

// ---------------- head ----------------
__global__ void head_kernel(const float* __restrict__ act, const float* __restrict__ beta,
                            float* __restrict__ out)
{
    const int t = blockIdx.x;
    const int b = threadIdx.x;
    float s = 0.f;
#pragma unroll 8
    for (int o = 0; o < 256; o++)
        s += act[b * 256 + o] * __ldg(&beta[o * 10 + t]);
    out[b * 10 + t] = s * (1.0f / 256.0f);
}

// ---------------- launch ----------------
extern "C" void kernel_launch(void* const* d_in, const int* in_sizes, int n_in,
                              void* d_out, int out_size)
{
    const float* x = (const float*)d_in[0];
    const float* wl[10];
    for (int l = 0; l < 10; l++) wl[l] = (const float*)d_in[1 + l];
    const float* beta = (const float*)d_in[11];
    float* out = (float*)d_out;

    float *bufA, *bufB, *part;
    cudaGetSymbolAddress((void**)&bufA, g_bufA);
    cudaGetSymbolAddress((void**)&bufB, g_bufB);
    cudaGetSymbolAddress((void**)&part, g_part);

    cudaFuncSetAttribute(lc_mma, cudaFuncAttributeMaxDynamicSharedMemorySize, SMEM_BYTES);

    layer0_kernel<<<512, 256>>>(x, wl[0], bufA);

    float* cur = bufA;
    float* nxt = bufB;
    int dl = 256;
    const float scale = 0.0625f;
    for (int l = 1; l <= 9; l++) {
        int S;
        if (dl >= 128)     S = 1;
        else if (dl == 64) S = 2;
        else if (dl == 32) S = 4;
        else               S = 8;
        const int nst = 16 / S;
        if (S == 1) {
            lc_mma<<<dim3(dl, 1), 256, SMEM_BYTES>>>(cur, wl[l], nxt, dl, nst, scale, 0);
        } else {
            lc_mma<<<dim3(dl, S), 256, SMEM_BYTES>>>(cur, wl[l], part, dl, nst, scale, 1);
            const int n = dl * 32768;
            reduce_relu_kernel<<<(n + 255) / 256, 256>>>(part, nxt, n, dl, S, scale);
        }
        float* tmp = cur; cur = nxt; nxt = tmp;
        dl >>= 1;
    }

    head_kernel<<<10, 128>>>(cur, beta, out);
}

// round 13
// speedup vs baseline: 1.0114x; 1.0078x over previous
#include <cuda_runtime.h>
#include <cuda_fp16.h>
#include <cstdint>

typedef unsigned long long u64;

// ---------------- static scratch ----------------
// activations layout: (p, b, c) : act[(p*128 + b)*256 + c]
__device__ __align__(16) float g_bufA[512 * 128 * 256];   // 67 MB
__device__ __align__(16) float g_bufB[256 * 128 * 256];   // 33.5 MB
__device__ __align__(16) float g_part[4194304];           // 16.8 MB split-K partials

// ---------------- helpers ----------------
__device__ __forceinline__ uint32_t s2u(const void* p) {
    uint32_t a;
    asm("{\n\t.reg .u64 t;\n\tcvta.to.shared.u64 t, %1;\n\tcvt.u32.u64 %0, t;\n\t}" : "=r"(a) : "l"(p));
    return a;
}
// pack two f32 -> f16x2: first arg -> low half, second -> high half
__device__ __forceinline__ uint32_t packh(float lo, float hi) {
    uint32_t r;
    asm("cvt.rn.f16x2.f32 %0, %1, %2;" : "=r"(r) : "f"(hi), "f"(lo));
    return r;
}
__device__ __forceinline__ void split2(float x0, float x1, uint32_t& hi, uint32_t& lo) {
    uint32_t h = packh(x0, x1);
    __half2 h2 = *(__half2*)&h;
    float r0 = x0 - __half2float(h2.x);
    float r1 = x1 - __half2float(h2.y);
    lo = packh(r0, r1);
    hi = h;
}
__device__ __forceinline__ void ldsm4(uint32_t* r, uint32_t addr) {
    asm volatile("ldmatrix.sync.aligned.m8n8.x4.shared.b16 {%0,%1,%2,%3}, [%4];"
        : "=r"(r[0]), "=r"(r[1]), "=r"(r[2]), "=r"(r[3]) : "r"(addr));
}
__device__ __forceinline__ void mma16816(float* d, const uint32_t* a, uint32_t b0, uint32_t b1) {
    asm volatile("mma.sync.aligned.m16n8k16.row.col.f32.f16.f16.f32 "
        "{%0,%1,%2,%3}, {%4,%5,%6,%7}, {%8,%9}, {%0,%1,%2,%3};"
        : "+f"(d[0]), "+f"(d[1]), "+f"(d[2]), "+f"(d[3])
        : "r"(a[0]), "r"(a[1]), "r"(a[2]), "r"(a[3]), "r"(b0), "r"(b1));
}

// ---------------- layer 0 ----------------
__global__ void layer0_kernel(const float* __restrict__ x, const float* __restrict__ w0,
                              float* __restrict__ out)
{
    __shared__ float xs[6][128];
    const int d   = blockIdx.x;
    const int tid = threadIdx.x;
#pragma unroll
    for (int i = 0; i < 3; i++) {
        int e = tid + i * 256;
        int ck = e >> 7, b = e & 127;
        int c = ck >> 1, k = ck & 1;
        xs[ck][b] = x[(b * 3 + c) * 1024 + 2 * d + k];
    }
    __syncthreads();
    const int b  = tid & 127;
    const int oh = tid >> 7;
    const float2* w2 = (const float2*)w0;
    for (int o = oh; o < 256; o += 2) {
        float acc = 0.f;
#pragma unroll
        for (int c = 0; c < 3; c++) {
            float2 wv = w2[(o * 3 + c) * 512 + d];
            acc += xs[c * 2 + 0][b] * wv.x + xs[c * 2 + 1][b] * wv.y;
        }
        out[((size_t)d * 128 + b) * 256 + o] = fmaxf(acc * 0.5773502691896258f, 0.f);
    }
}

// ---------------- layers 1..9: warp-mma fp16x3, CTA 128x256, warp tile 64x64 ----------------
// in : (p, b, c)  C=256, B=128 ; w : (256, 256, dl, 2)
// CTA: M=128(b) x N=256(all o) x K-slice (nst*32), kappa = 2c+k
// smem stage: A tile 128x128B (16KB) + B tile 256x128B (32KB)
// Row layout: linear kappa — bytes [0,64) hi plane, [64,128) lo plane; SW128 swizzle.
#define SMEM_BYTES 98304

__global__ __launch_bounds__(256)
void lc_mma(const float* __restrict__ in, const float* __restrict__ w,
            float* __restrict__ out, int dl, int nst, float scale, int partial)
{
    extern __shared__ __align__(1024) char smem[];
    const uint32_t sb = s2u(smem);
    const int tid  = threadIdx.x;
    const int wid  = tid >> 5, lane = tid & 31;
    const int d    = blockIdx.x;
    const int s    = blockIdx.y;
    const int cbase = s * nst * 16;

    // ---- A loader roles: row r = b, channel-half h ----
    const int r  = tid >> 1;
    const int h  = tid & 1;
    const float*  a0p = in + ((size_t)(2 * d) * 128 + r) * 256;
    const float*  a1p = a0p + 128 * 256;
    const uint32_t rowb = (uint32_t)r * 128, xs_ = (uint32_t)(r & 7) << 4;
    const uint32_t offH0 = rowb + (((uint32_t)(2 * h) * 16) ^ xs_);
    const uint32_t offH1 = rowb + (((uint32_t)(2 * h + 1) * 16) ^ xs_);
    const uint32_t offL0 = rowb + (((uint32_t)(4 + 2 * h) * 16) ^ xs_);
    const uint32_t offL1 = rowb + (((uint32_t)(5 + 2 * h) * 16) ^ xs_);

    // ---- B loader roles: one thread per o row ----
    const int ob = tid;
    const float2* w2 = (const float2*)w;
    const size_t  wrow = (size_t)ob * 256;
    const uint32_t rowbB = (uint32_t)ob * 128, xsB = (uint32_t)(ob & 7) << 4;
    uint32_t offBH[4], offBL[4];
#pragma unroll
    for (int g = 0; g < 4; g++) {
        offBH[g] = rowbB + (((uint32_t)(g * 16)) ^ xsB);
        offBL[g] = rowbB + (((uint32_t)(64 + g * 16)) ^ xsB);
    }

    const uint32_t ST[2] = { sb, sb + 49152 };

    // ---- compute roles: 2(M) x 4(N) warps, warp tile 64x64 ----
    const int mh = wid & 1, nq = wid >> 1;
    const uint32_t co = (uint32_t)(lane >> 4) * 16;
    const uint32_t xa = (uint32_t)(lane & 7) << 4;
    uint32_t rA[4], rB[4];
#pragma unroll
    for (int mi = 0; mi < 4; mi++) rA[mi] = (uint32_t)(mh * 64 + mi * 16 + (lane & 15)) * 128;
#pragma unroll
    for (int bj = 0; bj < 4; bj++) rB[bj] = (uint32_t)(nq * 64 + bj * 16 + (lane & 15)) * 128;

    float D[4][8][4];
#pragma unroll
    for (int i = 0; i < 4; i++)
#pragma unroll
        for (int j = 0; j < 8; j++)
#pragma unroll
            for (int q = 0; q < 4; q++) D[i][j][q] = 0.f;

    float  fa[16];
    float2 fb[16];

    auto issue_loads = [&](int t) {
        const int c0a = cbase + t * 16 + 8 * h;
        *(float4*)&fa[0]  = *(const float4*)(a0p + c0a);
        *(float4*)&fa[4]  = *(const float4*)(a0p + c0a + 4);
        *(float4*)&fa[8]  = *(const float4*)(a1p + c0a);
        *(float4*)&fa[12] = *(const float4*)(a1p + c0a + 4);
        const int c0b = cbase + t * 16;
#pragma unroll
        for (int j = 0; j < 16; j++)
            fb[j] = w2[(wrow + (size_t)(c0b + j)) * dl + d];
    };

    auto convert_store = [&](int buf) {
        uint32_t Ah[8], Al[8];
#pragma unroll
        for (int j = 0; j < 8; j++)
            split2(fa[j], fa[8 + j], Ah[j], Al[j]);
        const uint32_t ab = ST[buf];
        asm volatile("st.shared.v4.b32 [%0], {%1,%2,%3,%4};" :: "r"(ab + offH0), "r"(Ah[0]), "r"(Ah[1]), "r"(Ah[2]), "r"(Ah[3]));
        asm volatile("st.shared.v4.b32 [%0], {%1,%2,%3,%4};" :: "r"(ab + offH1), "r"(Ah[4]), "r"(Ah[5]), "r"(Ah[6]), "r"(Ah[7]));
        asm volatile("st.shared.v4.b32 [%0], {%1,%2,%3,%4};" :: "r"(ab + offL0), "r"(Al[0]), "r"(Al[1]), "r"(Al[2]), "r"(Al[3]));
        asm volatile("st.shared.v4.b32 [%0], {%1,%2,%3,%4};" :: "r"(ab + offL1), "r"(Al[4]), "r"(Al[5]), "r"(Al[6]), "r"(Al[7]));
        const uint32_t bbx = ST[buf] + 16384;
#pragma unroll
        for (int g = 0; g < 4; g++) {
            uint32_t BH[4], BL[4];
#pragma unroll
            for (int m = 0; m < 4; m++)
                split2(fb[g * 4 + m].x, fb[g * 4 + m].y, BH[m], BL[m]);
            asm volatile("st.shared.v4.b32 [%0], {%1,%2,%3,%4};" :: "r"(bbx + offBH[g]), "r"(BH[0]), "r"(BH[1]), "r"(BH[2]), "r"(BH[3]));
            asm volatile("st.shared.v4.b32 [%0], {%1,%2,%3,%4};" :: "r"(bbx + offBL[g]), "r"(BL[0]), "r"(BL[1]), "r"(BL[2]), "r"(BL[3]));
        }
    };

    issue_loads(0);
    convert_store(0);
    __syncthreads();

    for (int t = 0; t < nst; t++) {
        const int buf = t & 1;
        if (t + 1 < nst) issue_loads(t + 1);

        const uint32_t ab = ST[buf], bb = ST[buf] + 16384;
#pragma unroll
        for (int kk = 0; kk < 2; kk++) {
            const uint32_t khi = (uint32_t)(32 * kk) + co;
            const uint32_t klo = khi + 64;
            uint32_t Ahf[4][4], Alf[4][4];
#pragma unroll
            for (int mi = 0; mi < 4; mi++) {
                ldsm4(Ahf[mi], ab + rA[mi] + (khi ^ xa));
                ldsm4(Alf[mi], ab + rA[mi] + (klo ^ xa));
            }
#pragma unroll
            for (int bj = 0; bj < 4; bj++) {
                uint32_t Bhf[4], Blf[4];
                ldsm4(Bhf, bb + rB[bj] + (khi ^ xa));
                ldsm4(Blf, bb + rB[bj] + (klo ^ xa));
                // three sweeps of 8 independent MMAs each:
                // same-accumulator writes are 8 issues apart (no RAW back-to-back)
#pragma unroll
                for (int mi = 0; mi < 4; mi++)
#pragma unroll
                    for (int ns = 0; ns < 2; ns++)
                        mma16816(D[mi][bj * 2 + ns], Ahf[mi], Bhf[ns], Bhf[ns + 2]);
#pragma unroll
                for (int mi = 0; mi < 4; mi++)
#pragma unroll
                    for (int ns = 0; ns < 2; ns++)
                        mma16816(D[mi][bj * 2 + ns], Alf[mi], Bhf[ns], Bhf[ns + 2]);
#pragma unroll
                for (int mi = 0; mi < 4; mi++)
#pragma unroll
                    for (int ns = 0; ns < 2; ns++)
                        mma16816(D[mi][bj * 2 + ns], Ahf[mi], Blf[ns], Blf[ns + 2]);
            }
        }

        if (t + 1 < nst) convert_store(buf ^ 1);
        __syncthreads();
    }

    // ---- epilogue ----
    const int colq = nq * 64 + 2 * (lane & 3);
    if (partial) {
        float* pp = g_part + ((size_t)s * dl + d) * 32768;
#pragma unroll
        for (int mi = 0; mi < 4; mi++) {
            const int b0 = mh * 64 + mi * 16 + (lane >> 2);
#pragma unroll
            for (int nj = 0; nj < 8; nj++) {
                const int col = colq + nj * 8;
                *(float2*)(pp + (size_t)b0 * 256 + col)       = make_float2(D[mi][nj][0], D[mi][nj][1]);
                *(float2*)(pp + (size_t)(b0 + 8) * 256 + col) = make_float2(D[mi][nj][2], D[mi][nj][3]);
            }
        }
    } else {
        float* op = out + (size_t)d * 128 * 256;
#pragma unroll
        for (int mi = 0; mi < 4; mi++) {
            const int b0 = mh * 64 + mi * 16 + (lane >> 2);
#pragma unroll
            for (int nj = 0; nj < 8; nj++) {
                const int col = colq + nj * 8;
                float2 v0 = make_float2(fmaxf(D[mi][nj][0] * scale, 0.f), fmaxf(D[mi][nj][1] * scale, 0.f));
                float2 v1 = make_float2(fmaxf(D[mi][nj][2] * scale, 0.f), fmaxf(D[mi][nj][3] * scale, 0.f));
                *(float2*)(op + (size_t)b0 * 256 + col)       = v0;
                *(float2*)(op + (size_t)(b0 + 8) * 256 + col) = v1;
            }
        }
    }
}

// ---------------- split-K reduce + relu ----------------
__global__ void reduce_relu_kernel(const float* __restrict__ part, float* __restrict__ out,
                                   int n, int dl, int S, float scale)
{
    int idx = blockIdx.x * 256 + threadIdx.x;
    if (idx >= n) return;
    const int dd  = idx >> 15;
    const int rem = idx & 32767;
    float sum = 0.f;
    for (int si = 0; si < S; si++)
        sum += part[((size_t)si * dl + dd) * 32768 + rem];
    out[idx] = fmaxf(sum * scale, 0.f);
}

// ---------------- head ----------------
__global__ void head_kernel(const float* __restrict__ act, const float* __restrict__ beta,
                            float* __restrict__ out)
{
    const int t = blockIdx.x;
    const int b = threadIdx.x;
    float s = 0.f;
#pragma unroll 8
    for (int o = 0; o < 256; o++)
        s += act[b * 256 + o] * __ldg(&beta[o * 10 + t]);
    out[b * 10 + t] = s * (1.0f / 256.0f);
}

// ---------------- launch ----------------
extern "C" void kernel_launch(void* const* d_in, const int* in_sizes, int n_in,
                              void* d_out, int out_size)
{
    const float* x = (const float*)d_in[0];
    const float* wl[10];
    for (int l = 0; l < 10; l++) wl[l] = (const float*)d_in[1 + l];
    const float* beta = (const float*)d_in[11];
    float* out = (float*)d_out;

    float *bufA, *bufB, *part;
    cudaGetSymbolAddress((void**)&bufA, g_bufA);
    cudaGetSymbolAddress((void**)&bufB, g_bufB);
    cudaGetSymbolAddress((void**)&part, g_part);

    cudaFuncSetAttribute(lc_mma, cudaFuncAttributeMaxDynamicSharedMemorySize, SMEM_BYTES);

    layer0_kernel<<<512, 256>>>(x, wl[0], bufA);

    float* cur = bufA;
    float* nxt = bufB;
    int dl = 256;
    const float scale = 0.0625f;
    for (int l = 1; l <= 9; l++) {
        int S;
        if (dl >= 128)     S = 1;
        else if (dl == 64) S = 2;
        else if (dl == 32) S = 4;
        else               S = 8;
        const int nst = 16 / S;
        if (S == 1) {
            lc_mma<<<dim3(dl, 1), 256, SMEM_BYTES>>>(cur, wl[l], nxt, dl, nst, scale, 0);
        } else {
            lc_mma<<<dim3(dl, S), 256, SMEM_BYTES>>>(cur, wl[l], part, dl, nst, scale, 1);
            const int n = dl * 32768;
            reduce_relu_kernel<<<(n + 255) / 256, 256>>>(part, nxt, n, dl, S, scale);
        }
        float* tmp = cur; cur = nxt; nxt = tmp;
        dl >>= 1;
    }

    head_kernel<<<10, 128>>>(cur, beta, out);
}